// round 15
// baseline (speedup 1.0000x reference)
#include <cuda_runtime.h>
#include <cstdint>

#define BB 32
#define SS 128
#define EE 512
#define FF 2048

// scratch: h = x@W1 + b1  [s][b][f]   (33.5 MB)
__device__ __align__(16) float g_h[(size_t)SS * BB * FF];
// scratch: y = h@W2 + b2 + x  [b][s][e]  (8.4 MB)
__device__ __align__(16) float g_y[(size_t)BB * SS * EE];
// per-half LN partials: [half][s][b] = (sum, sumsq)
__device__ float2 g_part[2][SS][BB];

// Shared-stage geometry (floats): A[32][36], B[32][264]  (R9 known-good)
#define ASTR 36
#define BSTR 264
#define ABYTES (32 * ASTR * 4)                 // 4608
#define BBYTES (32 * BSTR * 4)                 // 33792
#define NSTG 3
#define DYN_TOTAL (NSTG * (ABYTES + BBYTES))   // 115200 -> 2 CTAs/SM (232448+2KB resv fits 228KB)

__device__ __forceinline__ uint32_t smem_u32(const void* p) {
    uint32_t a;
    asm("{ .reg .u64 t; cvta.to.shared.u64 t, %1; cvt.u32.u64 %0, t; }" : "=r"(a) : "l"(p));
    return a;
}
__device__ __forceinline__ void cp16(uint32_t saddr, const float* g) {
    asm volatile("cp.async.cg.shared.global [%0], [%1], 16;" :: "r"(saddr), "l"(g) : "memory");
}
__device__ __forceinline__ void cp_commit() { asm volatile("cp.async.commit_group;" ::: "memory"); }
template<int N> __device__ __forceinline__ void cp_wait() {
    asm volatile("cp.async.wait_group %0;" :: "n"(N) : "memory");
}
__device__ __forceinline__ uint32_t f2tf(float f) {
    uint32_t r; asm("cvt.rna.tf32.f32 %0, %1;" : "=r"(r) : "f"(f)); return r;
}
// D(16x8) += A(16x8,row) * B(8x8,col), tf32 inputs, f32 accum
__device__ __forceinline__ void mma8(float* c, const uint32_t* a, const uint32_t* b) {
    asm volatile("mma.sync.aligned.m16n8k8.row.col.f32.tf32.tf32.f32 "
        "{%0,%1,%2,%3}, {%4,%5,%6,%7}, {%8,%9}, {%0,%1,%2,%3};"
        : "+f"(c[0]), "+f"(c[1]), "+f"(c[2]), "+f"(c[3])
        : "r"(a[0]), "r"(a[1]), "r"(a[2]), "r"(a[3]), "r"(b[0]), "r"(b[1]));
}

// ---------------------------------------------------------------------------
// R9 configuration with a 3-deep cp.async buffer (dual-sync schedule kept).
//  G2=false: h[s][b][ft:ft+256] = x[b][s][:] @ W1[s][:, ft:] + b1   grid (8, 128)
//  G2=true : y[b][s][ft:ft+256] = h[s][b][:] @ W2[s][:, ft:] + b2 + x,
//            plus per-half (sum, sumsq) partials                    grid (2, 128)
// 256 threads = 8 warps; warp w owns CTA-local cols [w*32, w*32+32).
// C tile M=32 (batch) x N=256, K in 32-chunks. 2 CTAs/SM.
// ---------------------------------------------------------------------------
template<bool G2>
__global__ __launch_bounds__(256, 2) void ffn_kernel(
    const float* __restrict__ x, const float* __restrict__ W,
    const float* __restrict__ bias)
{
    constexpr int KD  = G2 ? FF : EE;   // reduction dim
    constexpr int NC  = G2 ? EE : FF;   // W row width
    constexpr int NCH = KD / 32;

    extern __shared__ __align__(16) char dyn[];
    float* Apt[NSTG]; float* Bpt[NSTG];
    uint32_t aAddr[NSTG], bAddr[NSTG];
    const uint32_t dynb = smem_u32(dyn);
    #pragma unroll
    for (int i = 0; i < NSTG; i++) {
        Apt[i] = (float*)(dyn + i * ABYTES);
        Bpt[i] = (float*)(dyn + NSTG * ABYTES + i * BBYTES);
        aAddr[i] = dynb + i * ABYTES;
        bAddr[i] = dynb + NSTG * ABYTES + i * BBYTES;
    }

    __shared__ float s_sum[8][32], s_sq[8][32];

    const int tid = threadIdx.x;
    const int w   = tid >> 5;
    const int l   = tid & 31;
    const int r   = l >> 2;       // groupID
    const int cl  = l & 3;        // threadID-in-group
    const int s   = (int)blockIdx.y;
    const int ft  = (int)blockIdx.x * 256;

    auto fillA = [&](int st, int kc) {
        int row = tid >> 3, seg = tid & 7;
        const float* g = G2 ? (g_h + ((size_t)s * BB + row) * FF + kc + seg * 4)
                            : (x   + ((size_t)row * SS + s) * EE + kc + seg * 4);
        cp16(aAddr[st] + row * (ASTR * 4) + seg * 16, g);
    };
    auto fillB = [&](int st, int kc) {
        const float* wb = W + ((size_t)s * KD + kc) * NC + ft;
        #pragma unroll
        for (int it = 0; it < 8; it++) {
            int idx = it * 256 + tid;
            int kr = idx >> 6, ns = idx & 63;   // ns = 16B unit along N (256 cols)
            cp16(bAddr[st] + kr * (BSTR * 4) + ns * 16, wb + (size_t)kr * NC + ns * 4);
        }
    };

    float acc[2][4][4] = {};    // [mTile][nTile][reg]

    // prologue: 2 chunks in flight
    fillA(0, 0);  fillB(0, 0);  cp_commit();
    fillA(1, 32); fillB(1, 32); cp_commit();

    for (int c = 0; c < NCH; c++) {
        const int cur = c % NSTG;
        // issue fill for c+2 first (targets stage freed by sync#2 of iter c-1)
        if (c + 2 < NCH) {
            fillA((c + 2) % NSTG, (c + 2) * 32);
            fillB((c + 2) % NSTG, (c + 2) * 32);
            cp_commit();
            cp_wait<2>();              // fills c+1, c+2 may remain pending
        } else if (c + 1 < NCH) {
            cp_wait<1>();              // fill c+1 may remain pending
        } else {
            cp_wait<0>();
        }
        __syncthreads();               // sync#1: stage cur visible to all

        // A fragments (converted once, reused by all n-tiles)
        const float* Ac = Apt[cur];
        uint32_t afr[2][4][4];
        #pragma unroll
        for (int mt = 0; mt < 2; mt++)
            #pragma unroll
            for (int ks = 0; ks < 4; ks++) {
                int rb = mt * 16 + r, kb = ks * 8 + cl;
                afr[mt][ks][0] = f2tf(Ac[rb * ASTR + kb]);
                afr[mt][ks][1] = f2tf(Ac[(rb + 8) * ASTR + kb]);
                afr[mt][ks][2] = f2tf(Ac[rb * ASTR + kb + 4]);
                afr[mt][ks][3] = f2tf(Ac[(rb + 8) * ASTR + kb + 4]);
            }

        const float* Bc = Bpt[cur];
        const int nb = w * 32 + r;
        #pragma unroll
        for (int nt = 0; nt < 4; nt++) {
            #pragma unroll
            for (int ks = 0; ks < 4; ks++) {
                // raw fp32 bits: HMMA.TF32 truncates the mantissa in HW
                uint32_t bfr[2];
                bfr[0] = __float_as_uint(Bc[(ks * 8 + cl) * BSTR + nb + nt * 8]);
                bfr[1] = __float_as_uint(Bc[(ks * 8 + 4 + cl) * BSTR + nb + nt * 8]);
                mma8(acc[0][nt], afr[0][ks], bfr);
                mma8(acc[1][nt], afr[1][ks], bfr);
            }
        }
        __syncthreads();               // sync#2: stage cur free for refill
    }

    if (!G2) {
        // epilogue 1: h = C + b1
        const float* bp = bias + (size_t)s * NC + ft;
        #pragma unroll
        for (int mt = 0; mt < 2; mt++)
            #pragma unroll
            for (int nt = 0; nt < 4; nt++) {
                int n0 = w * 32 + nt * 8 + 2 * cl;
                int m0 = mt * 16 + r;
                float b0 = bp[n0], b1v = bp[n0 + 1];
                float2 v0 = make_float2(acc[mt][nt][0] + b0, acc[mt][nt][1] + b1v);
                float2 v1 = make_float2(acc[mt][nt][2] + b0, acc[mt][nt][3] + b1v);
                *reinterpret_cast<float2*>(&g_h[((size_t)s * BB + m0) * FF + ft + n0]) = v0;
                *reinterpret_cast<float2*>(&g_h[((size_t)s * BB + m0 + 8) * FF + ft + n0]) = v1;
            }
    } else {
        // stage this half's x residual rows into Bpt[0] (coalesced)
        #pragma unroll
        for (int it = 0; it < 8; it++) {
            int idx = it * 256 + tid;
            int row = idx >> 6, ns = idx & 63;
            cp16(bAddr[0] + row * (BSTR * 4) + ns * 16,
                 x + ((size_t)row * SS + s) * EE + ft + ns * 4);
        }
        cp_commit(); cp_wait<0>();
        __syncthreads();

        const float* xs = Bpt[0];
        const float* bp = bias + (size_t)s * EE + ft;

        float sums[4] = {0.f, 0.f, 0.f, 0.f};
        float sqs[4]  = {0.f, 0.f, 0.f, 0.f};
        #pragma unroll
        for (int mt = 0; mt < 2; mt++)
            #pragma unroll
            for (int nt = 0; nt < 4; nt++) {
                int n0 = w * 32 + nt * 8 + 2 * cl;
                int m0 = mt * 16 + r;
                float b0 = bp[n0], b1v = bp[n0 + 1];
                float y0 = acc[mt][nt][0] + b0  + xs[m0 * BSTR + n0];
                float y1 = acc[mt][nt][1] + b1v + xs[m0 * BSTR + n0 + 1];
                float y2 = acc[mt][nt][2] + b0  + xs[(m0 + 8) * BSTR + n0];
                float y3 = acc[mt][nt][3] + b1v + xs[(m0 + 8) * BSTR + n0 + 1];
                *reinterpret_cast<float2*>(&g_y[((size_t)m0 * SS + s) * EE + ft + n0])
                    = make_float2(y0, y1);
                *reinterpret_cast<float2*>(&g_y[((size_t)(m0 + 8) * SS + s) * EE + ft + n0])
                    = make_float2(y2, y3);
                sums[mt * 2 + 0] += y0 + y1;  sqs[mt * 2 + 0] += y0 * y0 + y1 * y1;
                sums[mt * 2 + 1] += y2 + y3;  sqs[mt * 2 + 1] += y2 * y2 + y3 * y3;
            }
        // reduce over the 4 lanes sharing a row (cl = 0..3)
        #pragma unroll
        for (int o = 1; o <= 2; o <<= 1) {
            #pragma unroll
            for (int i = 0; i < 4; i++) {
                sums[i] += __shfl_xor_sync(0xffffffffu, sums[i], o);
                sqs[i]  += __shfl_xor_sync(0xffffffffu, sqs[i],  o);
            }
        }
        if (cl == 0) {
            s_sum[w][r]      = sums[0];  s_sq[w][r]      = sqs[0];
            s_sum[w][r + 8]  = sums[1];  s_sq[w][r + 8]  = sqs[1];
            s_sum[w][r + 16] = sums[2];  s_sq[w][r + 16] = sqs[2];
            s_sum[w][r + 24] = sums[3];  s_sq[w][r + 24] = sqs[3];
        }
        __syncthreads();
        if (tid < 32) {
            float t = 0.f, q = 0.f;
            #pragma unroll
            for (int ww = 0; ww < 8; ww++) { t += s_sum[ww][tid]; q += s_sq[ww][tid]; }
            g_part[blockIdx.x][s][tid] = make_float2(t, q);   // deterministic, no atomics
        }
    }
}

// ---------------------------------------------------------------------------
// LN finalize: out[b][s][:] = (y - mu) * rsqrt(var + eps) * gamma + beta
// grid 128 (one CTA per s), 256 threads.
// ---------------------------------------------------------------------------
__global__ __launch_bounds__(256) void ln_kernel(
    const float* __restrict__ gamma, const float* __restrict__ beta,
    float* __restrict__ out)
{
    __shared__ float s_mu[BB], s_rs[BB];
    const int s   = blockIdx.x;
    const int tid = threadIdx.x;
    const int w   = tid >> 5;
    const int l   = tid & 31;

    if (tid < BB) {
        float2 p0 = g_part[0][s][tid];
        float2 p1 = g_part[1][s][tid];
        float sum = p0.x + p1.x, sq = p0.y + p1.y;
        float mu  = sum * (1.f / EE);
        s_mu[tid] = mu;
        s_rs[tid] = rsqrtf(sq * (1.f / EE) - mu * mu + 1e-5f);
    }
    __syncthreads();

    #pragma unroll
    for (int j = 0; j < 4; j++) {
        int b = w + j * 8;
        float mu = s_mu[b], rs = s_rs[b];
        const float4* yp = reinterpret_cast<const float4*>(
            g_y + ((size_t)b * SS + s) * EE);
        float4* op = reinterpret_cast<float4*>(out + ((size_t)b * SS + s) * EE);
        #pragma unroll
        for (int i = 0; i < 4; i++) {
            int idx = l + i * 32;                    // float4 index 0..127
            float4 y  = yp[idx];
            float4 g4 = reinterpret_cast<const float4*>(gamma)[idx];
            float4 e4 = reinterpret_cast<const float4*>(beta)[idx];
            float4 v;
            v.x = (y.x - mu) * rs * g4.x + e4.x;
            v.y = (y.y - mu) * rs * g4.y + e4.y;
            v.z = (y.z - mu) * rs * g4.z + e4.z;
            v.w = (y.w - mu) * rs * g4.w + e4.w;
            op[idx] = v;
        }
    }
}

extern "C" void kernel_launch(void* const* d_in, const int* in_sizes, int n_in,
                              void* d_out, int out_size) {
    const float* x     = (const float*)d_in[0];
    const float* W1    = (const float*)d_in[1];
    const float* b1    = (const float*)d_in[2];
    const float* W2    = (const float*)d_in[3];
    const float* b2    = (const float*)d_in[4];
    const float* gamma = (const float*)d_in[5];
    const float* beta  = (const float*)d_in[6];
    float* out = (float*)d_out;

    cudaFuncSetAttribute(ffn_kernel<false>,
                         cudaFuncAttributeMaxDynamicSharedMemorySize, DYN_TOTAL);
    cudaFuncSetAttribute(ffn_kernel<true>,
                         cudaFuncAttributeMaxDynamicSharedMemorySize, DYN_TOTAL);

    ffn_kernel<false><<<dim3(FF / 256, SS), 256, DYN_TOTAL>>>(x, W1, b1);
    ffn_kernel<true ><<<dim3(EE / 256, SS), 256, DYN_TOTAL>>>(x, W2, b2);
    ln_kernel<<<SS, 256>>>(gamma, beta, out);
}

// round 16
// speedup vs baseline: 1.2120x; 1.2120x over previous
#include <cuda_runtime.h>
#include <cstdint>

#define BB 32
#define SS 128
#define EE 512
#define FF 2048

// scratch: h = x@W1 + b1  [s][b][f]   (33.5 MB)
__device__ __align__(16) float g_h[(size_t)SS * BB * FF];
// scratch: y = h@W2 + b2 + x  [b][s][e]  (8.4 MB)
__device__ __align__(16) float g_y[(size_t)BB * SS * EE];
// per-half LN partials: [half][s][b] = (sum, sumsq)
__device__ float2 g_part[2][SS][BB];

// Shared-stage geometry (floats): A[32][36], B[32][264]  (R9 known-good)
#define ASTR 36
#define BSTR 264
#define ABYTES (32 * ASTR * 4)                 // 4608
#define BBYTES (32 * BSTR * 4)                 // 33792
#define DYN_TOTAL (2 * (ABYTES + BBYTES))      // 76800

__device__ __forceinline__ uint32_t smem_u32(const void* p) {
    uint32_t a;
    asm("{ .reg .u64 t; cvta.to.shared.u64 t, %1; cvt.u32.u64 %0, t; }" : "=r"(a) : "l"(p));
    return a;
}
__device__ __forceinline__ void cp16(uint32_t saddr, const float* g) {
    asm volatile("cp.async.cg.shared.global [%0], [%1], 16;" :: "r"(saddr), "l"(g) : "memory");
}
__device__ __forceinline__ void cp_commit() { asm volatile("cp.async.commit_group;" ::: "memory"); }
template<int N> __device__ __forceinline__ void cp_wait() {
    asm volatile("cp.async.wait_group %0;" :: "n"(N) : "memory");
}
__device__ __forceinline__ uint32_t f2tf(float f) {
    uint32_t r; asm("cvt.rna.tf32.f32 %0, %1;" : "=r"(r) : "f"(f)); return r;
}
// D(16x8) += A(16x8,row) * B(8x8,col), tf32 inputs, f32 accum
__device__ __forceinline__ void mma8(float* c, const uint32_t* a, const uint32_t* b) {
    asm volatile("mma.sync.aligned.m16n8k8.row.col.f32.tf32.tf32.f32 "
        "{%0,%1,%2,%3}, {%4,%5,%6,%7}, {%8,%9}, {%0,%1,%2,%3};"
        : "+f"(c[0]), "+f"(c[1]), "+f"(c[2]), "+f"(c[3])
        : "r"(a[0]), "r"(a[1]), "r"(a[2]), "r"(a[3]), "r"(b[0]), "r"(b[1]));
}

// ---------------------------------------------------------------------------
// R9 configuration, byte-identical (measured 228.1us, GEMM1 at 71.5% HBM):
//  G2=false: h[s][b][ft:ft+256] = x[b][s][:] @ W1[s][:, ft:] + b1   grid (8, 128)
//  G2=true : y[b][s][ft:ft+256] = h[s][b][:] @ W2[s][:, ft:] + b2 + x,
//            plus per-half (sum, sumsq) partials                    grid (2, 128)
// 256 threads = 8 warps; warp w owns CTA-local cols [w*32, w*32+32).
// C tile M=32 (batch) x N=256, K streamed in 32-chunks, 2-stage cp.async.
// 2 CTAs per SM (77KB smem, <=128 regs).
// ---------------------------------------------------------------------------
template<bool G2>
__global__ __launch_bounds__(256, 2) void ffn_kernel(
    const float* __restrict__ x, const float* __restrict__ W,
    const float* __restrict__ bias)
{
    constexpr int KD  = G2 ? FF : EE;   // reduction dim
    constexpr int NC  = G2 ? EE : FF;   // W row width
    constexpr int NCH = KD / 32;

    extern __shared__ __align__(16) char dyn[];
    float* Apt[2] = { (float*)dyn, (float*)(dyn + ABYTES) };
    float* Bpt[2] = { (float*)(dyn + 2 * ABYTES), (float*)(dyn + 2 * ABYTES + BBYTES) };
    const uint32_t aAddr[2] = { smem_u32(Apt[0]), smem_u32(Apt[1]) };
    const uint32_t bAddr[2] = { smem_u32(Bpt[0]), smem_u32(Bpt[1]) };

    __shared__ float s_sum[8][32], s_sq[8][32];

    const int tid = threadIdx.x;
    const int w   = tid >> 5;
    const int l   = tid & 31;
    const int r   = l >> 2;       // groupID
    const int cl  = l & 3;        // threadID-in-group
    const int s   = (int)blockIdx.y;
    const int ft  = (int)blockIdx.x * 256;

    auto fillA = [&](int st, int kc) {
        int row = tid >> 3, seg = tid & 7;
        const float* g = G2 ? (g_h + ((size_t)s * BB + row) * FF + kc + seg * 4)
                            : (x   + ((size_t)row * SS + s) * EE + kc + seg * 4);
        cp16(aAddr[st] + row * (ASTR * 4) + seg * 16, g);
    };
    auto fillB = [&](int st, int kc) {
        const float* wb = W + ((size_t)s * KD + kc) * NC + ft;
        #pragma unroll
        for (int it = 0; it < 8; it++) {
            int idx = it * 256 + tid;
            int kr = idx >> 6, ns = idx & 63;   // ns = 16B unit along N (256 cols)
            cp16(bAddr[st] + kr * (BSTR * 4) + ns * 16, wb + (size_t)kr * NC + ns * 4);
        }
    };

    float acc[2][4][4] = {};    // [mTile][nTile][reg]

    fillA(0, 0); fillB(0, 0); cp_commit();

    for (int c = 0; c < NCH; c++) {
        const int cur = c & 1;
        if (c + 1 < NCH) {
            fillA(1 - cur, (c + 1) * 32);
            fillB(1 - cur, (c + 1) * 32);
            cp_commit();
            cp_wait<1>();
        } else {
            cp_wait<0>();
        }
        __syncthreads();

        // A fragments for this chunk (converted once, reused by all n-tiles)
        const float* Ac = Apt[cur];
        uint32_t afr[2][4][4];
        #pragma unroll
        for (int mt = 0; mt < 2; mt++)
            #pragma unroll
            for (int ks = 0; ks < 4; ks++) {
                int rb = mt * 16 + r, kb = ks * 8 + cl;
                afr[mt][ks][0] = f2tf(Ac[rb * ASTR + kb]);
                afr[mt][ks][1] = f2tf(Ac[(rb + 8) * ASTR + kb]);
                afr[mt][ks][2] = f2tf(Ac[rb * ASTR + kb + 4]);
                afr[mt][ks][3] = f2tf(Ac[(rb + 8) * ASTR + kb + 4]);
            }

        const float* Bc = Bpt[cur];
        const int nb = w * 32 + r;
        #pragma unroll
        for (int nt = 0; nt < 4; nt++) {
            #pragma unroll
            for (int ks = 0; ks < 4; ks++) {
                // raw fp32 bits: HMMA.TF32 truncates the mantissa in hardware
                uint32_t bfr[2];
                bfr[0] = __float_as_uint(Bc[(ks * 8 + cl) * BSTR + nb + nt * 8]);
                bfr[1] = __float_as_uint(Bc[(ks * 8 + 4 + cl) * BSTR + nb + nt * 8]);
                mma8(acc[0][nt], afr[0][ks], bfr);
                mma8(acc[1][nt], afr[1][ks], bfr);
            }
        }
        __syncthreads();
    }

    if (!G2) {
        // epilogue 1: h = C + b1
        const float* bp = bias + (size_t)s * NC + ft;
        #pragma unroll
        for (int mt = 0; mt < 2; mt++)
            #pragma unroll
            for (int nt = 0; nt < 4; nt++) {
                int n0 = w * 32 + nt * 8 + 2 * cl;
                int m0 = mt * 16 + r;
                float b0 = bp[n0], b1v = bp[n0 + 1];
                float2 v0 = make_float2(acc[mt][nt][0] + b0, acc[mt][nt][1] + b1v);
                float2 v1 = make_float2(acc[mt][nt][2] + b0, acc[mt][nt][3] + b1v);
                *reinterpret_cast<float2*>(&g_h[((size_t)s * BB + m0) * FF + ft + n0]) = v0;
                *reinterpret_cast<float2*>(&g_h[((size_t)s * BB + m0 + 8) * FF + ft + n0]) = v1;
            }
    } else {
        // stage this half's x residual rows into Bpt[0] (coalesced)
        #pragma unroll
        for (int it = 0; it < 8; it++) {
            int idx = it * 256 + tid;
            int row = idx >> 6, ns = idx & 63;
            cp16(bAddr[0] + row * (BSTR * 4) + ns * 16,
                 x + ((size_t)row * SS + s) * EE + ft + ns * 4);
        }
        cp_commit(); cp_wait<0>();
        __syncthreads();

        const float* xs = Bpt[0];
        const float* bp = bias + (size_t)s * EE + ft;

        float sums[4] = {0.f, 0.f, 0.f, 0.f};
        float sqs[4]  = {0.f, 0.f, 0.f, 0.f};
        #pragma unroll
        for (int mt = 0; mt < 2; mt++)
            #pragma unroll
            for (int nt = 0; nt < 4; nt++) {
                int n0 = w * 32 + nt * 8 + 2 * cl;
                int m0 = mt * 16 + r;
                float b0 = bp[n0], b1v = bp[n0 + 1];
                float y0 = acc[mt][nt][0] + b0  + xs[m0 * BSTR + n0];
                float y1 = acc[mt][nt][1] + b1v + xs[m0 * BSTR + n0 + 1];
                float y2 = acc[mt][nt][2] + b0  + xs[(m0 + 8) * BSTR + n0];
                float y3 = acc[mt][nt][3] + b1v + xs[(m0 + 8) * BSTR + n0 + 1];
                *reinterpret_cast<float2*>(&g_y[((size_t)m0 * SS + s) * EE + ft + n0])
                    = make_float2(y0, y1);
                *reinterpret_cast<float2*>(&g_y[((size_t)(m0 + 8) * SS + s) * EE + ft + n0])
                    = make_float2(y2, y3);
                sums[mt * 2 + 0] += y0 + y1;  sqs[mt * 2 + 0] += y0 * y0 + y1 * y1;
                sums[mt * 2 + 1] += y2 + y3;  sqs[mt * 2 + 1] += y2 * y2 + y3 * y3;
            }
        // reduce over the 4 lanes sharing a row (cl = 0..3)
        #pragma unroll
        for (int o = 1; o <= 2; o <<= 1) {
            #pragma unroll
            for (int i = 0; i < 4; i++) {
                sums[i] += __shfl_xor_sync(0xffffffffu, sums[i], o);
                sqs[i]  += __shfl_xor_sync(0xffffffffu, sqs[i],  o);
            }
        }
        if (cl == 0) {
            s_sum[w][r]      = sums[0];  s_sq[w][r]      = sqs[0];
            s_sum[w][r + 8]  = sums[1];  s_sq[w][r + 8]  = sqs[1];
            s_sum[w][r + 16] = sums[2];  s_sq[w][r + 16] = sqs[2];
            s_sum[w][r + 24] = sums[3];  s_sq[w][r + 24] = sqs[3];
        }
        __syncthreads();
        if (tid < 32) {
            float t = 0.f, q = 0.f;
            #pragma unroll
            for (int ww = 0; ww < 8; ww++) { t += s_sum[ww][tid]; q += s_sq[ww][tid]; }
            g_part[blockIdx.x][s][tid] = make_float2(t, q);   // deterministic, no atomics
        }
    }
}

// ---------------------------------------------------------------------------
// LN finalize, parallelized: grid (4, 128) = 512 CTAs; CTA (q, s) normalizes
// e-quarter [q*128, q*128+128) of all 32 batch rows for position s.
// out[b][s][e] = (y - mu) * rsqrt(var + eps) * gamma + beta
// 256 threads = 8 warps; warp w handles rows w*4..w*4+3, lane l -> float4 col l.
// ---------------------------------------------------------------------------
__global__ __launch_bounds__(256) void ln_kernel(
    const float* __restrict__ gamma, const float* __restrict__ beta,
    float* __restrict__ out)
{
    __shared__ float s_mu[BB], s_rs[BB];
    const int s    = (int)blockIdx.y;
    const int q4   = (int)blockIdx.x * 32;   // float4 offset of this e-quarter
    const int tid  = threadIdx.x;
    const int w    = tid >> 5;
    const int l    = tid & 31;

    if (tid < BB) {
        float2 p0 = g_part[0][s][tid];
        float2 p1 = g_part[1][s][tid];
        float sum = p0.x + p1.x, sq = p0.y + p1.y;
        float mu  = sum * (1.f / EE);
        s_mu[tid] = mu;
        s_rs[tid] = rsqrtf(sq * (1.f / EE) - mu * mu + 1e-5f);
    }
    __syncthreads();

    const int idx = q4 + l;                                  // float4 index in row
    const float4 g4 = reinterpret_cast<const float4*>(gamma)[idx];
    const float4 e4 = reinterpret_cast<const float4*>(beta)[idx];

    #pragma unroll
    for (int j = 0; j < 4; j++) {
        int b = w * 4 + j;
        float mu = s_mu[b], rs = s_rs[b];
        const size_t off4 = (((size_t)b * SS + s) * EE) >> 2;
        float4 y = reinterpret_cast<const float4*>(g_y)[off4 + idx];
        float4 v;
        v.x = (y.x - mu) * rs * g4.x + e4.x;
        v.y = (y.y - mu) * rs * g4.y + e4.y;
        v.z = (y.z - mu) * rs * g4.z + e4.z;
        v.w = (y.w - mu) * rs * g4.w + e4.w;
        reinterpret_cast<float4*>(out)[off4 + idx] = v;
    }
}

extern "C" void kernel_launch(void* const* d_in, const int* in_sizes, int n_in,
                              void* d_out, int out_size) {
    const float* x     = (const float*)d_in[0];
    const float* W1    = (const float*)d_in[1];
    const float* b1    = (const float*)d_in[2];
    const float* W2    = (const float*)d_in[3];
    const float* b2    = (const float*)d_in[4];
    const float* gamma = (const float*)d_in[5];
    const float* beta  = (const float*)d_in[6];
    float* out = (float*)d_out;

    cudaFuncSetAttribute(ffn_kernel<false>,
                         cudaFuncAttributeMaxDynamicSharedMemorySize, DYN_TOTAL);
    cudaFuncSetAttribute(ffn_kernel<true>,
                         cudaFuncAttributeMaxDynamicSharedMemorySize, DYN_TOTAL);

    ffn_kernel<false><<<dim3(FF / 256, SS), 256, DYN_TOTAL>>>(x, W1, b1);
    ffn_kernel<true ><<<dim3(EE / 256, SS), 256, DYN_TOTAL>>>(x, W2, b2);
    ln_kernel<<<dim3(4, SS), 256>>>(gamma, beta, out);
}